// round 7
// baseline (speedup 1.0000x reference)
#include <cuda_runtime.h>
#include <cstdint>
#include <cstddef>

#define T_STEPS 2048
#define BATCH   64
#define DIM     256
#define HID     256
#define NLAYER  2
#define GDIM    1024                    // 4*H
#define MROWS   (T_STEPS * BATCH)       // 131072

// h_s layout: row stride 264 (=8 mod 32), k<128 at [0,128), k>=128 at [132,260)
#define HS_STRIDE 264
#define HS_K1OFF  132
// Whs layout: khalf=0 at [0,2048), khalf=1 at [2064, 2064+2048)
#define WHS_H     2064

// ---------------- scratch (static device memory; no allocation APIs) -------
__device__ float    g_pre[(size_t)NLAYER * MROWS * GDIM];   // 1 GiB
__device__ float    g_h[NLAYER][2][BATCH * HID];            // double-buffered h
__device__ unsigned g_cnt[NLAYER];                          // arrival counters

// ---------------- packed fp32x2 helpers ------------------------------------
__device__ __forceinline__ unsigned long long pack2(float x, float y) {
    unsigned long long r;
    asm("mov.b64 %0, {%1, %2};" : "=l"(r) : "f"(x), "f"(y));
    return r;
}
__device__ __forceinline__ void unpack2(unsigned long long v, float& x, float& y) {
    asm("mov.b64 {%0, %1}, %2;" : "=f"(x), "=f"(y) : "l"(v));
}
__device__ __forceinline__ void fma2(unsigned long long& d, unsigned long long a,
                                     unsigned long long b) {
    asm("fma.rn.f32x2 %0, %1, %2, %0;" : "+l"(d) : "l"(a), "l"(b));
}

__device__ __forceinline__ float sigmoidf_(float x) {
    return 1.0f / (1.0f + expf(-x));
}

// ---------------- kernel 1: pre[l,t,b,:] = x[t,b,:] @ Wx[l] + b[l] ---------
__global__ __launch_bounds__(256, 2) void k_pre(const float* __restrict__ x,
                                                const float* __restrict__ W,
                                                const float* __restrict__ bias) {
    __shared__ __align__(16) float As[32 * 132];   // [k][m], padded
    __shared__ __align__(16) float Bs[32 * 128];   // [k][n]

    if (blockIdx.x == 0 && threadIdx.x < NLAYER) g_cnt[threadIdx.x] = 0u;

    int bid  = blockIdx.x;
    int l    = bid >> 13;
    int rem  = bid & 8191;
    int mt   = rem >> 3;
    int nt   = rem & 7;
    int row0 = mt << 7;
    int col0 = nt << 7;
    int tid  = threadIdx.x;
    int tm   = tid >> 4;
    int tn   = tid & 15;

    const float* Wl = W + (size_t)l * 512 * 1024;

    unsigned long long acc[8][4];
#pragma unroll
    for (int i = 0; i < 8; i++)
#pragma unroll
        for (int j = 0; j < 4; j++) acc[i][j] = 0ULL;

    for (int kc = 0; kc < 256; kc += 32) {
#pragma unroll
        for (int i = 0; i < 4; i++) {
            int aidx = tid + i * 256;
            int m    = aidx >> 3;
            int k4   = (aidx & 7) << 2;
            float4 v = *(const float4*)&x[(size_t)(row0 + m) * 256 + kc + k4];
            As[(k4 + 0) * 132 + m] = v.x;
            As[(k4 + 1) * 132 + m] = v.y;
            As[(k4 + 2) * 132 + m] = v.z;
            As[(k4 + 3) * 132 + m] = v.w;
        }
#pragma unroll
        for (int i = 0; i < 4; i++) {
            int kk = (tid >> 5) + i * 8;
            int n4 = (tid & 31) << 2;
            *(float4*)&Bs[kk * 128 + n4] =
                *(const float4*)&Wl[(size_t)(kc + kk) * 1024 + col0 + n4];
        }
        __syncthreads();

#pragma unroll
        for (int k = 0; k < 32; k++) {
            float4 a0 = *(const float4*)&As[k * 132 + tm * 8];
            float4 a1 = *(const float4*)&As[k * 132 + tm * 8 + 4];
            ulonglong2 bb01 = *(const ulonglong2*)&Bs[k * 128 + tn * 8];
            ulonglong2 bb23 = *(const ulonglong2*)&Bs[k * 128 + tn * 8 + 4];
            float av[8] = {a0.x, a0.y, a0.z, a0.w, a1.x, a1.y, a1.z, a1.w};
#pragma unroll
            for (int i = 0; i < 8; i++) {
                unsigned long long a2 = pack2(av[i], av[i]);
                fma2(acc[i][0], a2, bb01.x);
                fma2(acc[i][1], a2, bb01.y);
                fma2(acc[i][2], a2, bb23.x);
                fma2(acc[i][3], a2, bb23.y);
            }
        }
        __syncthreads();
    }

    float bv[8];
#pragma unroll
    for (int j = 0; j < 8; j++) bv[j] = bias[l * 1024 + col0 + tn * 8 + j];
#pragma unroll
    for (int i = 0; i < 8; i++) {
        float o[8];
#pragma unroll
        for (int j = 0; j < 4; j++) unpack2(acc[i][j], o[2 * j], o[2 * j + 1]);
#pragma unroll
        for (int j = 0; j < 8; j++) o[j] += bv[j];
        size_t base = ((size_t)l * MROWS + row0 + tm * 8 + i) * 1024 + col0 + tn * 8;
        *(float4*)&g_pre[base]     = make_float4(o[0], o[1], o[2], o[3]);
        *(float4*)&g_pre[base + 4] = make_float4(o[4], o[5], o[6], o[7]);
    }
}

// ---------------- kernel 2: persistent recurrence ---------------------------
// 128 CTAs = 2 layers x 64 column-groups (4 h-cols). 512 threads:
// b = tid>>3, cq = (tid>>1)&3, khalf = tid&1. Each thread computes the
// half-dot over its k range; pairs combine via shfl_xor(1).
__global__ __launch_bounds__(512, 1) void k_rec(const float* __restrict__ h0,
                                                const float* __restrict__ c0,
                                                const float* __restrict__ W,
                                                float* __restrict__ out) {
    extern __shared__ float smem[];
    float* Whs = smem;                       // 2*2064 floats
    float* h_s = smem + 2 * WHS_H;           // 64 x 264

    int l     = blockIdx.x >> 6;
    int cg    = blockIdx.x & 63;
    int c0col = cg << 2;
    int tid   = threadIdx.x;
    int b     = tid >> 3;
    int cq    = (tid >> 1) & 3;
    int khalf = tid & 1;
    int hcol  = c0col + cq;

    // Wh slice -> smem, [khalf-section][k][cq][gate]
    const float* Whl = W + (size_t)l * 512 * 1024 + (size_t)256 * 1024;
    for (int i = tid; i < 4096; i += 512) {
        int k = i >> 4;
        int r = i & 15;
        int q = r >> 2;
        int g = r & 3;
        int dst = (k < 128 ? k * 16 : WHS_H + (k - 128) * 16) + r;
        Whs[dst] = Whl[(size_t)k * 1024 + g * 256 + c0col + q];
    }

    // stage initial h0
    const float* hsrc0 = h0 + l * BATCH * HID;
    for (int i = tid; i < 4096; i += 512) {
        int bb = i >> 6;
        int k4 = (i & 63) << 2;
        int ko = k4 + ((k4 >> 7) << 2);      // +4 pad for k>=128
        *(float4*)&h_s[bb * HS_STRIDE + ko] = *(const float4*)&hsrc0[bb * 256 + k4];
    }
    float c = c0[l * BATCH * HID + b * 256 + hcol];
    __syncthreads();

    const float* wb_ptr = Whs + khalf * WHS_H + cq * 4;
    const float* hrow   = h_s + b * HS_STRIDE + khalf * HS_K1OFF;
    float h_cur = 0.0f;

    for (int t = 0; t < T_STEPS; t++) {
        size_t prow = ((size_t)l * MROWS + (size_t)t * BATCH + b) * 1024 + hcol;
        float pf = __ldcs(&g_pre[prow]);
        float pi = __ldcs(&g_pre[prow + 256]);
        float pg = __ldcs(&g_pre[prow + 512]);
        float po = __ldcs(&g_pre[prow + 768]);

        // half-dot over 128 k values, 4 independent chains
        unsigned long long fiA = 0ULL, goA = 0ULL, fiB = 0ULL, goB = 0ULL;
#pragma unroll 8
        for (int k4 = 0; k4 < 128; k4 += 8) {
            float4 hv0 = *(const float4*)&hrow[k4];
            float4 hv1 = *(const float4*)&hrow[k4 + 4];
            float hh[8] = {hv0.x, hv0.y, hv0.z, hv0.w, hv1.x, hv1.y, hv1.z, hv1.w};
#pragma unroll
            for (int j = 0; j < 8; j++) {
                ulonglong2 wv = *(const ulonglong2*)&wb_ptr[(k4 + j) * 16];
                unsigned long long a2 = pack2(hh[j], hh[j]);
                if (j & 1) { fma2(fiB, a2, wv.x); fma2(goB, a2, wv.y); }
                else       { fma2(fiA, a2, wv.x); fma2(goA, a2, wv.y); }
            }
        }
        float af0, ai0, ag0, ao0, af1, ai1, ag1, ao1;
        unpack2(fiA, af0, ai0);
        unpack2(fiB, af1, ai1);
        unpack2(goA, ag0, ao0);
        unpack2(goB, ag1, ao1);
        float af = af0 + af1, ai = ai0 + ai1, ag = ag0 + ag1, ao = ao0 + ao1;
        // combine k-halves (partner = adjacent lane)
        af += __shfl_xor_sync(0xFFFFFFFFu, af, 1);
        ai += __shfl_xor_sync(0xFFFFFFFFu, ai, 1);
        ag += __shfl_xor_sync(0xFFFFFFFFu, ag, 1);
        ao += __shfl_xor_sync(0xFFFFFFFFu, ao, 1);

        float gf  = sigmoidf_(af + pf);
        float gi  = sigmoidf_(ai + pi);
        float gg  = tanhf(ag + pg);
        float go_ = sigmoidf_(ao + po);
        c     = gf * c + gi * gg;
        h_cur = go_ * tanhf(c);

        int wb = 1 - (t & 1);
        if (khalf == 0) {
            g_h[l][wb][b * 256 + hcol] = h_cur;
            if (l == 1) out[(size_t)t * BATCH * HID + b * 256 + hcol] = h_cur;
        }

        if (t == T_STEPS - 1) break;

        __syncthreads();
        if (tid == 0) {
            asm volatile("red.release.gpu.global.add.u32 [%0], %1;"
                         :: "l"(&g_cnt[l]), "r"(1u) : "memory");
            unsigned target = 64u * (unsigned)(t + 1);
            unsigned v;
            do {
                asm volatile("ld.acquire.gpu.global.u32 %0, [%1];"
                             : "=r"(v) : "l"(&g_cnt[l]) : "memory");
            } while (v < target);
        }
        __syncthreads();

        const float* hsrc = g_h[l][wb];
#pragma unroll 4
        for (int i = tid; i < 4096; i += 512) {
            int bb = i >> 6;
            int k4 = (i & 63) << 2;
            int ko = k4 + ((k4 >> 7) << 2);
            float4 v = __ldcg((const float4*)&hsrc[bb * 256 + k4]);
            *(float4*)&h_s[bb * HS_STRIDE + ko] = v;
        }
        __syncthreads();
    }

    if (khalf == 0) {
        size_t OUTH = (size_t)T_STEPS * BATCH * HID;
        out[OUTH + (size_t)l * BATCH * HID + b * 256 + hcol]                   = h_cur;
        out[OUTH + (size_t)NLAYER * BATCH * HID + (size_t)l * BATCH * HID
            + b * 256 + hcol]                                                   = c;
    }
}

// ---------------- launch ----------------------------------------------------
extern "C" void kernel_launch(void* const* d_in, const int* in_sizes, int n_in,
                              void* d_out, int out_size) {
    const float* x    = (const float*)d_in[0];
    const float* h0   = (const float*)d_in[1];
    const float* c0   = (const float*)d_in[2];
    const float* W    = (const float*)d_in[3];
    const float* bias = (const float*)d_in[4];
    float* out = (float*)d_out;

    size_t dsmem = (size_t)(2 * WHS_H + 64 * HS_STRIDE) * sizeof(float);  // 84,096 B
    cudaFuncSetAttribute(k_rec, cudaFuncAttributeMaxDynamicSharedMemorySize,
                         (int)dsmem);

    k_pre<<<NLAYER * (MROWS / 128) * (GDIM / 128), 256>>>(x, W, bias);
    k_rec<<<NLAYER * 64, 512, dsmem>>>(h0, c0, W, out);
}

// round 8
// speedup vs baseline: 1.5337x; 1.5337x over previous
#include <cuda_runtime.h>
#include <cstdint>
#include <cstddef>

#define T_STEPS 2048
#define BATCH   64
#define HID     256
#define NLAYER  2
#define MROWS   (T_STEPS * BATCH)       // 131072

// ---------------- scratch (static device memory; no allocation APIs) -------
__device__ float    g_pre[(size_t)NLAYER * MROWS * 1024];   // 1 GiB
__device__ float    g_h[NLAYER][2][HID * BATCH];            // TRANSPOSED [j][b]
__device__ unsigned g_cnt[NLAYER];

// ---------------- packed fp32x2 helpers ------------------------------------
__device__ __forceinline__ unsigned long long pack2(float x, float y) {
    unsigned long long r;
    asm("mov.b64 %0, {%1, %2};" : "=l"(r) : "f"(x), "f"(y));
    return r;
}
__device__ __forceinline__ void unpack2(unsigned long long v, float& x, float& y) {
    asm("mov.b64 {%0, %1}, %2;" : "=f"(x), "=f"(y) : "l"(v));
}
__device__ __forceinline__ void fma2(unsigned long long& d, unsigned long long a,
                                     unsigned long long b) {
    asm("fma.rn.f32x2 %0, %1, %2, %0;" : "+l"(d) : "l"(a), "l"(b));
}
__device__ __forceinline__ unsigned long long add2(unsigned long long a,
                                                   unsigned long long b) {
    unsigned long long r;
    asm("add.rn.f32x2 %0, %1, %2;" : "=l"(r) : "l"(a), "l"(b));
    return r;
}
__device__ __forceinline__ float sigmoidf_(float x) {
    return 1.0f / (1.0f + expf(-x));
}

// ---------------- kernel 1: pre[l,t,b,:] = x[t,b,:] @ Wx[l] + b[l] ---------
__global__ __launch_bounds__(256, 2) void k_pre(const float* __restrict__ x,
                                                const float* __restrict__ W,
                                                const float* __restrict__ bias) {
    __shared__ __align__(16) float As[32 * 132];
    __shared__ __align__(16) float Bs[32 * 128];

    if (blockIdx.x == 0 && threadIdx.x < NLAYER) g_cnt[threadIdx.x] = 0u;

    int bid  = blockIdx.x;
    int l    = bid >> 13;
    int rem  = bid & 8191;
    int mt   = rem >> 3;
    int nt   = rem & 7;
    int row0 = mt << 7;
    int col0 = nt << 7;
    int tid  = threadIdx.x;
    int tm   = tid >> 4;
    int tn   = tid & 15;

    const float* Wl = W + (size_t)l * 512 * 1024;

    unsigned long long acc[8][4];
#pragma unroll
    for (int i = 0; i < 8; i++)
#pragma unroll
        for (int j = 0; j < 4; j++) acc[i][j] = 0ULL;

    for (int kc = 0; kc < 256; kc += 32) {
#pragma unroll
        for (int i = 0; i < 4; i++) {
            int aidx = tid + i * 256;
            int m    = aidx >> 3;
            int k4   = (aidx & 7) << 2;
            float4 v = *(const float4*)&x[(size_t)(row0 + m) * 256 + kc + k4];
            As[(k4 + 0) * 132 + m] = v.x;
            As[(k4 + 1) * 132 + m] = v.y;
            As[(k4 + 2) * 132 + m] = v.z;
            As[(k4 + 3) * 132 + m] = v.w;
        }
#pragma unroll
        for (int i = 0; i < 4; i++) {
            int kk = (tid >> 5) + i * 8;
            int n4 = (tid & 31) << 2;
            *(float4*)&Bs[kk * 128 + n4] =
                *(const float4*)&Wl[(size_t)(kc + kk) * 1024 + col0 + n4];
        }
        __syncthreads();

#pragma unroll
        for (int k = 0; k < 32; k++) {
            float4 a0 = *(const float4*)&As[k * 132 + tm * 8];
            float4 a1 = *(const float4*)&As[k * 132 + tm * 8 + 4];
            ulonglong2 bb01 = *(const ulonglong2*)&Bs[k * 128 + tn * 8];
            ulonglong2 bb23 = *(const ulonglong2*)&Bs[k * 128 + tn * 8 + 4];
            float av[8] = {a0.x, a0.y, a0.z, a0.w, a1.x, a1.y, a1.z, a1.w};
#pragma unroll
            for (int i = 0; i < 8; i++) {
                unsigned long long a2 = pack2(av[i], av[i]);
                fma2(acc[i][0], a2, bb01.x);
                fma2(acc[i][1], a2, bb01.y);
                fma2(acc[i][2], a2, bb23.x);
                fma2(acc[i][3], a2, bb23.y);
            }
        }
        __syncthreads();
    }

    float bv[8];
#pragma unroll
    for (int j = 0; j < 8; j++) bv[j] = bias[l * 1024 + col0 + tn * 8 + j];
#pragma unroll
    for (int i = 0; i < 8; i++) {
        float o[8];
#pragma unroll
        for (int j = 0; j < 4; j++) unpack2(acc[i][j], o[2 * j], o[2 * j + 1]);
#pragma unroll
        for (int j = 0; j < 8; j++) o[j] += bv[j];
        size_t base = ((size_t)l * MROWS + row0 + tm * 8 + i) * 1024 + col0 + tn * 8;
        __stcs((float4*)&g_pre[base],     make_float4(o[0], o[1], o[2], o[3]));
        __stcs((float4*)&g_pre[base + 4], make_float4(o[4], o[5], o[6], o[7]));
    }
}

// ---------------- kernel 2: persistent recurrence ---------------------------
// 128 CTAs = 2 layers x 64 col-groups (4 hcols). 512 threads = 16 warps.
// warp = b-group (4 b rows). lane = ks(3b)|ng(2b): ks = k-slice (32 k),
// ng = hcol within group. Thread: 4b x 4gates over its 32-k slice;
// butterfly-shfl over ks; lanes ks<4 do pointwise for b = b_lo+ks.
__global__ __launch_bounds__(512, 1) void k_rec(const float* __restrict__ h0,
                                                const float* __restrict__ c0,
                                                const float* __restrict__ W,
                                                float* __restrict__ out) {
    extern __shared__ float smem[];
    float* Whs = smem;            // 4096 floats: [k][ng*4+g]
    float* h_s = smem + 4096;     // 16384 floats: [k][b] (transposed)

    int l     = blockIdx.x >> 6;
    int cg    = blockIdx.x & 63;
    int c0col = cg << 2;
    int tid   = threadIdx.x;
    int bg    = tid >> 5;          // warp id = b-group
    int lane  = tid & 31;
    int ks    = lane >> 2;         // 0..7
    int ng    = lane & 3;          // hcol within group
    int b_lo  = bg << 2;
    int k0    = ks << 5;
    int hcol  = c0col + ng;
    bool pw   = (ks < 4);
    int  bpw  = b_lo + ks;         // pointwise batch row (valid if pw)

    // Wh slice -> smem, per-k gate-interleaved: Whs[k*16 + nq*4 + g]
    const float* Whl = W + (size_t)l * 512 * 1024 + (size_t)256 * 1024;
    for (int i = tid; i < 4096; i += 512) {
        int k = i >> 4, r = i & 15, nq = r >> 2, g = r & 3;
        Whs[i] = Whl[(size_t)k * 1024 + g * 256 + c0col + nq];
    }

    // stage h0 transposed -> h_s[j*64+b]
    const float* h0l = h0 + l * BATCH * HID;
    for (int i = tid; i < 16384; i += 512) {
        int j = i >> 6, bb = i & 63;
        h_s[i] = h0l[bb * 256 + j];
    }
    float c = 0.0f, h_cur = 0.0f;
    if (pw) c = c0[l * BATCH * HID + bpw * 256 + hcol];
    __syncthreads();

    const float* wp = Whs + (k0 << 4) + (ng << 2);
    const float* hp = h_s + (k0 << 6) + b_lo;

    for (int t = 0; t < T_STEPS; t++) {
        // prefetch pre-activations (independent of barrier)
        float4 pv = make_float4(0.f, 0.f, 0.f, 0.f);
        if (pw) {
            size_t prow = ((size_t)l * MROWS + (size_t)t * BATCH + bpw) * 1024 + hcol;
            pv.x = __ldcs(&g_pre[prow]);         // f
            pv.y = __ldcs(&g_pre[prow + 256]);   // i
            pv.z = __ldcs(&g_pre[prow + 512]);   // g
            pv.w = __ldcs(&g_pre[prow + 768]);   // o
        }

        // 4b x 4gates partial dot over 32 k (all smem loads broadcast)
        unsigned long long fi[4] = {0ULL, 0ULL, 0ULL, 0ULL};
        unsigned long long go[4] = {0ULL, 0ULL, 0ULL, 0ULL};
#pragma unroll 8
        for (int k = 0; k < 32; k++) {
            float4 hv = *(const float4*)&hp[k << 6];       // h[k][b_lo..+3]
            ulonglong2 wv = *(const ulonglong2*)&wp[k << 4]; // (wf,wi),(wg,wo)
            float hh[4] = {hv.x, hv.y, hv.z, hv.w};
#pragma unroll
            for (int bi = 0; bi < 4; bi++) {
                unsigned long long a2 = pack2(hh[bi], hh[bi]);
                fma2(fi[bi], a2, wv.x);
                fma2(go[bi], a2, wv.y);
            }
        }
        // butterfly-reduce over ks (lane strides 4, 8, 16)
#pragma unroll
        for (int s = 4; s <= 16; s <<= 1) {
#pragma unroll
            for (int bi = 0; bi < 4; bi++) {
                fi[bi] = add2(fi[bi], __shfl_xor_sync(0xFFFFFFFFu, fi[bi], s));
                go[bi] = add2(go[bi], __shfl_xor_sync(0xFFFFFFFFu, go[bi], s));
            }
        }

        if (pw) {
            float af, ai_, ag, ao;
            unpack2(fi[ks], af, ai_);
            unpack2(go[ks], ag, ao);
            float gf  = sigmoidf_(af + pv.x);
            float gi  = sigmoidf_(ai_ + pv.y);
            float gg  = tanhf(ag + pv.z);
            float go_ = sigmoidf_(ao + pv.w);
            c     = gf * c + gi * gg;
            h_cur = go_ * tanhf(c);
            g_h[l][1 - (t & 1)][hcol * 64 + bpw] = h_cur;     // transposed
            if (l == 1) out[(size_t)t * BATCH * HID + bpw * 256 + hcol] = h_cur;
        }

        if (t == T_STEPS - 1) break;

        __syncthreads();
        if (tid == 0) {
            asm volatile("red.release.gpu.global.add.u32 [%0], %1;"
                         :: "l"(&g_cnt[l]), "r"(1u) : "memory");
            unsigned target = 64u * (unsigned)(t + 1);
            unsigned v;
            do {
                asm volatile("ld.acquire.gpu.global.u32 %0, [%1];"
                             : "=r"(v) : "l"(&g_cnt[l]) : "memory");
            } while (v < target);
        }
        __syncthreads();

        // stage h_t: straight 64 KB copy (same [j][b] layout)
        const float4* src = (const float4*)g_h[l][1 - (t & 1)];
        float4* dst = (float4*)h_s;
#pragma unroll 4
        for (int i = tid; i < 4096; i += 512) dst[i] = __ldcg(&src[i]);
        __syncthreads();
    }

    if (pw) {
        size_t OUTH = (size_t)T_STEPS * BATCH * HID;
        out[OUTH + (size_t)l * BATCH * HID + bpw * 256 + hcol]                 = h_cur;
        out[OUTH + (size_t)NLAYER * BATCH * HID + (size_t)l * BATCH * HID
            + bpw * 256 + hcol]                                                 = c;
    }
}

// ---------------- launch ----------------------------------------------------
extern "C" void kernel_launch(void* const* d_in, const int* in_sizes, int n_in,
                              void* d_out, int out_size) {
    const float* x    = (const float*)d_in[0];
    const float* h0   = (const float*)d_in[1];
    const float* c0   = (const float*)d_in[2];
    const float* W    = (const float*)d_in[3];
    const float* bias = (const float*)d_in[4];
    float* out = (float*)d_out;

    size_t dsmem = (size_t)(4096 + 16384) * sizeof(float);   // 81,920 B
    cudaFuncSetAttribute(k_rec, cudaFuncAttributeMaxDynamicSharedMemorySize,
                         (int)dsmem);

    k_pre<<<NLAYER * (MROWS / 128) * (1024 / 128), 256>>>(x, W, bias);
    k_rec<<<NLAYER * 64, 512, dsmem>>>(h0, c0, W, out);
}

// round 9
// speedup vs baseline: 1.8586x; 1.2119x over previous
#include <cuda_runtime.h>
#include <cstdint>
#include <cstddef>

#define T_STEPS 2048
#define BATCH   64
#define HID     256
#define NLAYER  2
#define MROWS   (T_STEPS * BATCH)       // 131072

// swizzled smem layouts (pad one quad per 32-k slice to spread bank groups)
#define HS_SLICE  (32 * 64 + 4)         // 2052 floats per k-slice
#define WHS_SLICE (32 * 16 + 4)         // 516 floats per k-slice

// ---------------- scratch (static device memory; no allocation APIs) -------
__device__ float    g_pre[(size_t)NLAYER * MROWS * 1024];   // 1 GiB
__device__ float    g_h[NLAYER][2][HID * BATCH];            // TRANSPOSED [j][b]
__device__ unsigned g_cnt[NLAYER];

// ---------------- packed fp32x2 helpers ------------------------------------
__device__ __forceinline__ unsigned long long pack2(float x, float y) {
    unsigned long long r;
    asm("mov.b64 %0, {%1, %2};" : "=l"(r) : "f"(x), "f"(y));
    return r;
}
__device__ __forceinline__ void unpack2(unsigned long long v, float& x, float& y) {
    asm("mov.b64 {%0, %1}, %2;" : "=f"(x), "=f"(y) : "l"(v));
}
__device__ __forceinline__ void fma2(unsigned long long& d, unsigned long long a,
                                     unsigned long long b) {
    asm("fma.rn.f32x2 %0, %1, %2, %0;" : "+l"(d) : "l"(a), "l"(b));
}
__device__ __forceinline__ unsigned long long add2(unsigned long long a,
                                                   unsigned long long b) {
    unsigned long long r;
    asm("add.rn.f32x2 %0, %1, %2;" : "=l"(r) : "l"(a), "l"(b));
    return r;
}
__device__ __forceinline__ float sigmoidf_(float x) {
    return 1.0f / (1.0f + expf(-x));
}

// ---------------- kernel 1: pre[l,t,b,:] = x[t,b,:] @ Wx[l] + b[l] ---------
__global__ __launch_bounds__(256, 2) void k_pre(const float* __restrict__ x,
                                                const float* __restrict__ W,
                                                const float* __restrict__ bias) {
    __shared__ __align__(16) float As[32 * 132];
    __shared__ __align__(16) float Bs[32 * 128];

    if (blockIdx.x == 0 && threadIdx.x < NLAYER) g_cnt[threadIdx.x] = 0u;

    int bid  = blockIdx.x;
    int l    = bid >> 13;
    int rem  = bid & 8191;
    int mt   = rem >> 3;
    int nt   = rem & 7;
    int row0 = mt << 7;
    int col0 = nt << 7;
    int tid  = threadIdx.x;
    int tm   = tid >> 4;
    int tn   = tid & 15;

    const float* Wl = W + (size_t)l * 512 * 1024;

    unsigned long long acc[8][4];
#pragma unroll
    for (int i = 0; i < 8; i++)
#pragma unroll
        for (int j = 0; j < 4; j++) acc[i][j] = 0ULL;

    for (int kc = 0; kc < 256; kc += 32) {
#pragma unroll
        for (int i = 0; i < 4; i++) {
            int aidx = tid + i * 256;
            int m    = aidx >> 3;
            int k4   = (aidx & 7) << 2;
            float4 v = *(const float4*)&x[(size_t)(row0 + m) * 256 + kc + k4];
            As[(k4 + 0) * 132 + m] = v.x;
            As[(k4 + 1) * 132 + m] = v.y;
            As[(k4 + 2) * 132 + m] = v.z;
            As[(k4 + 3) * 132 + m] = v.w;
        }
#pragma unroll
        for (int i = 0; i < 4; i++) {
            int kk = (tid >> 5) + i * 8;
            int n4 = (tid & 31) << 2;
            *(float4*)&Bs[kk * 128 + n4] =
                *(const float4*)&Wl[(size_t)(kc + kk) * 1024 + col0 + n4];
        }
        __syncthreads();

#pragma unroll
        for (int k = 0; k < 32; k++) {
            float4 a0 = *(const float4*)&As[k * 132 + tm * 8];
            float4 a1 = *(const float4*)&As[k * 132 + tm * 8 + 4];
            ulonglong2 bb01 = *(const ulonglong2*)&Bs[k * 128 + tn * 8];
            ulonglong2 bb23 = *(const ulonglong2*)&Bs[k * 128 + tn * 8 + 4];
            float av[8] = {a0.x, a0.y, a0.z, a0.w, a1.x, a1.y, a1.z, a1.w};
#pragma unroll
            for (int i = 0; i < 8; i++) {
                unsigned long long a2 = pack2(av[i], av[i]);
                fma2(acc[i][0], a2, bb01.x);
                fma2(acc[i][1], a2, bb01.y);
                fma2(acc[i][2], a2, bb23.x);
                fma2(acc[i][3], a2, bb23.y);
            }
        }
        __syncthreads();
    }

    float bv[8];
#pragma unroll
    for (int j = 0; j < 8; j++) bv[j] = bias[l * 1024 + col0 + tn * 8 + j];
#pragma unroll
    for (int i = 0; i < 8; i++) {
        float o[8];
#pragma unroll
        for (int j = 0; j < 4; j++) unpack2(acc[i][j], o[2 * j], o[2 * j + 1]);
#pragma unroll
        for (int j = 0; j < 8; j++) o[j] += bv[j];
        size_t base = ((size_t)l * MROWS + row0 + tm * 8 + i) * 1024 + col0 + tn * 8;
        __stcs((float4*)&g_pre[base],     make_float4(o[0], o[1], o[2], o[3]));
        __stcs((float4*)&g_pre[base + 4], make_float4(o[4], o[5], o[6], o[7]));
    }
}

// ---------------- kernel 2: persistent recurrence ---------------------------
// 128 CTAs = 2 layers x 64 col-groups (4 hcols). 512 threads = 16 warps.
// warp = b-group (4 b rows). lane = ks(3b)|ng(2b). Swizzled smem:
//   h_s[j][b]  at  (j>>5)*HS_SLICE  + (j&31)*64 + b      (slice pad 4)
//   Whs[k][r]  at  (k>>5)*WHS_SLICE + (k&31)*16 + r      (slice pad 4)
// -> hv loads 1 phase (broadcast, distinct quads), wv loads 4 phases (floor).
__global__ __launch_bounds__(512, 1) void k_rec(const float* __restrict__ h0,
                                                const float* __restrict__ c0,
                                                const float* __restrict__ W,
                                                float* __restrict__ out) {
    extern __shared__ float smem[];
    float* Whs = smem;                          // 8*516 = 4128 floats
    float* h_s = smem + 8 * WHS_SLICE;          // 8*2052 = 16416 floats

    int l     = blockIdx.x >> 6;
    int cg    = blockIdx.x & 63;
    int c0col = cg << 2;
    int tid   = threadIdx.x;
    int bg    = tid >> 5;          // warp id = b-group
    int lane  = tid & 31;
    int ks    = lane >> 2;         // 0..7 (32-k slice)
    int ng    = lane & 3;          // hcol within group
    int b_lo  = bg << 2;
    int hcol  = c0col + ng;
    bool pw   = (ks < 4);
    int  bpw  = b_lo + ks;         // pointwise batch row (valid if pw)

    // Wh slice -> smem: Whs[(k>>5)*516 + (k&31)*16 + nq*4 + g]
    const float* Whl = W + (size_t)l * 512 * 1024 + (size_t)256 * 1024;
    for (int i = tid; i < 4096; i += 512) {
        int k = i >> 4, r = i & 15, nq = r >> 2, g = r & 3;
        Whs[(k >> 5) * WHS_SLICE + (k & 31) * 16 + r] =
            Whl[(size_t)k * 1024 + g * 256 + c0col + nq];
    }

    // stage h0 transposed + swizzled
    const float* h0l = h0 + l * BATCH * HID;
    for (int i = tid; i < 16384; i += 512) {
        int j = i >> 6, bb = i & 63;
        h_s[(j >> 5) * HS_SLICE + (j & 31) * 64 + bb] = h0l[bb * 256 + j];
    }
    float c = 0.0f, h_cur = 0.0f;
    if (pw) c = c0[l * BATCH * HID + bpw * 256 + hcol];
    __syncthreads();

    const float* wp = Whs + ks * WHS_SLICE + (ng << 2);
    const float* hp = h_s + ks * HS_SLICE + b_lo;

    for (int t = 0; t < T_STEPS; t++) {
        // prefetch pre-activations (independent of barrier)
        float4 pv = make_float4(0.f, 0.f, 0.f, 0.f);
        if (pw) {
            size_t prow = ((size_t)l * MROWS + (size_t)t * BATCH + bpw) * 1024 + hcol;
            pv.x = __ldcs(&g_pre[prow]);         // f
            pv.y = __ldcs(&g_pre[prow + 256]);   // i
            pv.z = __ldcs(&g_pre[prow + 512]);   // g
            pv.w = __ldcs(&g_pre[prow + 768]);   // o
        }

        // 4b x 4gates partial dot over this thread's 32-k slice
        unsigned long long fi[4] = {0ULL, 0ULL, 0ULL, 0ULL};
        unsigned long long go[4] = {0ULL, 0ULL, 0ULL, 0ULL};
#pragma unroll 8
        for (int k = 0; k < 32; k++) {
            float4 hv = *(const float4*)&hp[k << 6];         // h[k][b_lo..+3]
            ulonglong2 wv = *(const ulonglong2*)&wp[k << 4]; // (wf,wi),(wg,wo)
            float hh[4] = {hv.x, hv.y, hv.z, hv.w};
#pragma unroll
            for (int bi = 0; bi < 4; bi++) {
                unsigned long long a2 = pack2(hh[bi], hh[bi]);
                fma2(fi[bi], a2, wv.x);
                fma2(go[bi], a2, wv.y);
            }
        }
        // butterfly-reduce over ks (lane strides 4, 8, 16)
#pragma unroll
        for (int s = 4; s <= 16; s <<= 1) {
#pragma unroll
            for (int bi = 0; bi < 4; bi++) {
                fi[bi] = add2(fi[bi], __shfl_xor_sync(0xFFFFFFFFu, fi[bi], s));
                go[bi] = add2(go[bi], __shfl_xor_sync(0xFFFFFFFFu, go[bi], s));
            }
        }

        if (pw) {
            float af, ai_, ag, ao;
            unpack2(fi[ks], af, ai_);
            unpack2(go[ks], ag, ao);
            float gf  = sigmoidf_(af + pv.x);
            float gi  = sigmoidf_(ai_ + pv.y);
            float gg  = tanhf(ag + pv.z);
            float go_ = sigmoidf_(ao + pv.w);
            c     = gf * c + gi * gg;
            h_cur = go_ * tanhf(c);
            g_h[l][1 - (t & 1)][hcol * 64 + bpw] = h_cur;     // transposed
            if (l == 1) out[(size_t)t * BATCH * HID + bpw * 256 + hcol] = h_cur;
        }

        if (t == T_STEPS - 1) break;

        __syncthreads();
        if (tid == 0) {
            asm volatile("red.release.gpu.global.add.u32 [%0], %1;"
                         :: "l"(&g_cnt[l]), "r"(1u) : "memory");
            unsigned target = 64u * (unsigned)(t + 1);
            unsigned v;
            do {
                asm volatile("ld.acquire.gpu.global.u32 %0, [%1];"
                             : "=r"(v) : "l"(&g_cnt[l]) : "memory");
            } while (v < target);
        }
        __syncthreads();

        // stage h_t (swizzled dst: +1 float4 per 512-float4 slice)
        const float4* src = (const float4*)g_h[l][1 - (t & 1)];
        float4* dst = (float4*)h_s;
#pragma unroll 4
        for (int i = tid; i < 4096; i += 512) {
            dst[i + (i >> 9)] = __ldcg(&src[i]);
        }
        __syncthreads();
    }

    if (pw) {
        size_t OUTH = (size_t)T_STEPS * BATCH * HID;
        out[OUTH + (size_t)l * BATCH * HID + bpw * 256 + hcol]                 = h_cur;
        out[OUTH + (size_t)NLAYER * BATCH * HID + (size_t)l * BATCH * HID
            + bpw * 256 + hcol]                                                 = c;
    }
}

// ---------------- launch ----------------------------------------------------
extern "C" void kernel_launch(void* const* d_in, const int* in_sizes, int n_in,
                              void* d_out, int out_size) {
    const float* x    = (const float*)d_in[0];
    const float* h0   = (const float*)d_in[1];
    const float* c0   = (const float*)d_in[2];
    const float* W    = (const float*)d_in[3];
    const float* bias = (const float*)d_in[4];
    float* out = (float*)d_out;

    size_t dsmem = (size_t)(8 * WHS_SLICE + 8 * HS_SLICE) * sizeof(float); // 82,176 B
    cudaFuncSetAttribute(k_rec, cudaFuncAttributeMaxDynamicSharedMemorySize,
                         (int)dsmem);

    k_pre<<<NLAYER * (MROWS / 128) * (1024 / 128), 256>>>(x, W, bias);
    k_rec<<<NLAYER * 64, 512, dsmem>>>(h0, c0, W, out);
}

// round 10
// speedup vs baseline: 2.5386x; 1.3659x over previous
#include <cuda_runtime.h>
#include <cstdint>
#include <cstddef>

#define T_STEPS 2048
#define BATCH   64
#define HID     256
#define NLAYER  2
#define MROWS   (T_STEPS * BATCH)       // 131072

#define HS_SLICE  (32 * 64 + 4)         // 2052 floats per 32-k slice (bank swizzle)

// ---------------- scratch (static device memory; no allocation APIs) -------
__device__ float    g_pre[(size_t)NLAYER * MROWS * 1024];   // 1 GiB
__device__ float    g_h[NLAYER][2][HID * BATCH];            // TRANSPOSED [j][b]
__device__ unsigned g_cnt[NLAYER];

// ---------------- packed fp32x2 helpers ------------------------------------
__device__ __forceinline__ unsigned long long pack2(float x, float y) {
    unsigned long long r;
    asm("mov.b64 %0, {%1, %2};" : "=l"(r) : "f"(x), "f"(y));
    return r;
}
__device__ __forceinline__ void unpack2(unsigned long long v, float& x, float& y) {
    asm("mov.b64 {%0, %1}, %2;" : "=f"(x), "=f"(y) : "l"(v));
}
__device__ __forceinline__ void fma2(unsigned long long& d, unsigned long long a,
                                     unsigned long long b) {
    asm("fma.rn.f32x2 %0, %1, %2, %0;" : "+l"(d) : "l"(a), "l"(b));
}
__device__ __forceinline__ unsigned long long add2(unsigned long long a,
                                                   unsigned long long b) {
    unsigned long long r;
    asm("add.rn.f32x2 %0, %1, %2;" : "=l"(r) : "l"(a), "l"(b));
    return r;
}
__device__ __forceinline__ float sigmoidf_(float x) {
    return 1.0f / (1.0f + expf(-x));
}

// ---------------- kernel 1: pre[l,t,b,:] = x[t,b,:] @ Wx[l] + b[l] ---------
__global__ __launch_bounds__(256, 2) void k_pre(const float* __restrict__ x,
                                                const float* __restrict__ W,
                                                const float* __restrict__ bias) {
    __shared__ __align__(16) float As[32 * 132];
    __shared__ __align__(16) float Bs[32 * 128];

    if (blockIdx.x == 0 && threadIdx.x < NLAYER) g_cnt[threadIdx.x] = 0u;

    int bid  = blockIdx.x;
    int l    = bid >> 13;
    int rem  = bid & 8191;
    int mt   = rem >> 3;
    int nt   = rem & 7;
    int row0 = mt << 7;
    int col0 = nt << 7;
    int tid  = threadIdx.x;
    int tm   = tid >> 4;
    int tn   = tid & 15;

    const float* Wl = W + (size_t)l * 512 * 1024;

    unsigned long long acc[8][4];
#pragma unroll
    for (int i = 0; i < 8; i++)
#pragma unroll
        for (int j = 0; j < 4; j++) acc[i][j] = 0ULL;

    for (int kc = 0; kc < 256; kc += 32) {
#pragma unroll
        for (int i = 0; i < 4; i++) {
            int aidx = tid + i * 256;
            int m    = aidx >> 3;
            int k4   = (aidx & 7) << 2;
            float4 v = *(const float4*)&x[(size_t)(row0 + m) * 256 + kc + k4];
            As[(k4 + 0) * 132 + m] = v.x;
            As[(k4 + 1) * 132 + m] = v.y;
            As[(k4 + 2) * 132 + m] = v.z;
            As[(k4 + 3) * 132 + m] = v.w;
        }
#pragma unroll
        for (int i = 0; i < 4; i++) {
            int kk = (tid >> 5) + i * 8;
            int n4 = (tid & 31) << 2;
            *(float4*)&Bs[kk * 128 + n4] =
                *(const float4*)&Wl[(size_t)(kc + kk) * 1024 + col0 + n4];
        }
        __syncthreads();

#pragma unroll
        for (int k = 0; k < 32; k++) {
            float4 a0 = *(const float4*)&As[k * 132 + tm * 8];
            float4 a1 = *(const float4*)&As[k * 132 + tm * 8 + 4];
            ulonglong2 bb01 = *(const ulonglong2*)&Bs[k * 128 + tn * 8];
            ulonglong2 bb23 = *(const ulonglong2*)&Bs[k * 128 + tn * 8 + 4];
            float av[8] = {a0.x, a0.y, a0.z, a0.w, a1.x, a1.y, a1.z, a1.w};
#pragma unroll
            for (int i = 0; i < 8; i++) {
                unsigned long long a2 = pack2(av[i], av[i]);
                fma2(acc[i][0], a2, bb01.x);
                fma2(acc[i][1], a2, bb01.y);
                fma2(acc[i][2], a2, bb23.x);
                fma2(acc[i][3], a2, bb23.y);
            }
        }
        __syncthreads();
    }

    float bv[8];
#pragma unroll
    for (int j = 0; j < 8; j++) bv[j] = bias[l * 1024 + col0 + tn * 8 + j];
#pragma unroll
    for (int i = 0; i < 8; i++) {
        float o[8];
#pragma unroll
        for (int j = 0; j < 4; j++) unpack2(acc[i][j], o[2 * j], o[2 * j + 1]);
#pragma unroll
        for (int j = 0; j < 8; j++) o[j] += bv[j];
        size_t base = ((size_t)l * MROWS + row0 + tm * 8 + i) * 1024 + col0 + tn * 8;
        __stcs((float4*)&g_pre[base],     make_float4(o[0], o[1], o[2], o[3]));
        __stcs((float4*)&g_pre[base + 4], make_float4(o[4], o[5], o[6], o[7]));
    }
}

// ---------------- kernel 2: persistent recurrence ---------------------------
// 128 CTAs = 2 layers x 64 col-groups (4 hcols). 256 threads = 8 warps.
// warp = batch OCTET (8 b). lane = ks(3b)|ng(2b). W held in REGISTERS
// (32 k x 4 gates of 1 hcol = 64 packed u64) for the entire kernel.
// Dot loop smem traffic = h broadcast only (2 LDS.128 per k, 1 phase each).
// Reduce-scatter over ks -> every lane owns one (b, hcol) for pointwise.
__global__ __launch_bounds__(256, 1) void k_rec(const float* __restrict__ h0,
                                                const float* __restrict__ c0,
                                                const float* __restrict__ W,
                                                float* __restrict__ out) {
    extern __shared__ float smem[];
    float* h_s = smem;                      // 8*2052 = 16416 floats [j][b] swizzled

    int l     = blockIdx.x >> 6;
    int cg    = blockIdx.x & 63;
    int c0col = cg << 2;
    int tid   = threadIdx.x;
    int bg    = tid >> 5;          // warp id = batch octet
    int lane  = tid & 31;
    int ks    = lane >> 2;         // 32-k slice
    int ng    = lane & 3;          // hcol within group
    int b_lo  = bg << 3;
    int hcol  = c0col + ng;
    int b     = b_lo + ks;         // this lane's pointwise batch row

    // ---- W slice -> registers (persistent across all 2048 steps) ----
    unsigned long long wfi[32], wgo[32];
    {
        const float* Whl = W + (size_t)l * 512 * 1024 + (size_t)256 * 1024;
#pragma unroll
        for (int kk = 0; kk < 32; kk++) {
            const float* wr = Whl + (size_t)((ks << 5) + kk) * 1024 + hcol;
            wfi[kk] = pack2(wr[0], wr[256]);     // (f, i)
            wgo[kk] = pack2(wr[512], wr[768]);   // (g, o)
        }
    }

    // stage h0 transposed + swizzled: h_s[(j>>5)*2052 + (j&31)*64 + b]
    const float* h0l = h0 + l * BATCH * HID;
    for (int i = tid; i < 16384; i += 256) {
        int j = i >> 6, bb = i & 63;
        h_s[(j >> 5) * HS_SLICE + (j & 31) * 64 + bb] = h0l[bb * 256 + j];
    }
    float c = c0[l * BATCH * HID + b * 256 + hcol];
    float h_cur = 0.0f;
    __syncthreads();

    const float* hp = h_s + ks * HS_SLICE + b_lo;

    for (int t = 0; t < T_STEPS; t++) {
        // prefetch pre-activations (independent of everything below)
        size_t prow = ((size_t)l * MROWS + (size_t)t * BATCH + b) * 1024 + hcol;
        float pf = __ldcs(&g_pre[prow]);
        float pi = __ldcs(&g_pre[prow + 256]);
        float pg = __ldcs(&g_pre[prow + 512]);
        float po = __ldcs(&g_pre[prow + 768]);

        // 8b partial dot over this thread's 32-k slice; W from registers
        unsigned long long fi[8], go[8];
#pragma unroll
        for (int i = 0; i < 8; i++) { fi[i] = 0ULL; go[i] = 0ULL; }
#pragma unroll
        for (int kk = 0; kk < 32; kk++) {
            float4 hv0 = *(const float4*)&hp[kk << 6];
            float4 hv1 = *(const float4*)&hp[(kk << 6) + 4];
            float hh[8] = {hv0.x, hv0.y, hv0.z, hv0.w,
                           hv1.x, hv1.y, hv1.z, hv1.w};
#pragma unroll
            for (int bi = 0; bi < 8; bi++) {
                unsigned long long a2 = pack2(hh[bi], hh[bi]);
                fma2(fi[bi], a2, wfi[kk]);
                fma2(go[bi], a2, wgo[kk]);
            }
        }

        // reduce-scatter over ks: strides 16,8,4 <-> b-index bits 2,1,0.
        // After 3 rounds lane (ks,ng) holds the full sum for b = b_lo+ks.
#pragma unroll
        for (int r = 0; r < 3; r++) {
            int stride = 16 >> r;     // 16, 8, 4
            int half   = 4 >> r;      // 4, 2, 1
            bool hi = (lane & stride) != 0;
#pragma unroll
            for (int i = 0; i < 4; i++) {
                if (i < half) {
                    unsigned long long sf = hi ? fi[i] : fi[i + half];
                    unsigned long long kf = hi ? fi[i + half] : fi[i];
                    fi[i] = add2(kf, __shfl_xor_sync(0xFFFFFFFFu, sf, stride));
                    unsigned long long sg = hi ? go[i] : go[i + half];
                    unsigned long long kg = hi ? go[i + half] : go[i];
                    go[i] = add2(kg, __shfl_xor_sync(0xFFFFFFFFu, sg, stride));
                }
            }
        }

        // pointwise (every lane owns one (b, hcol))
        float af, ai_, ag, ao;
        unpack2(fi[0], af, ai_);
        unpack2(go[0], ag, ao);
        float gf  = sigmoidf_(af + pf);
        float gi  = sigmoidf_(ai_ + pi);
        float gg  = tanhf(ag + pg);
        float go_ = sigmoidf_(ao + po);
        c     = gf * c + gi * gg;
        h_cur = go_ * tanhf(c);

        int wb = 1 - (t & 1);
        g_h[l][wb][hcol * 64 + b] = h_cur;                    // transposed
        if (l == 1) out[(size_t)t * BATCH * HID + b * 256 + hcol] = h_cur;

        if (t == T_STEPS - 1) break;

        __syncthreads();
        if (tid == 0) {
            asm volatile("red.release.gpu.global.add.u32 [%0], %1;"
                         :: "l"(&g_cnt[l]), "r"(1u) : "memory");
            unsigned target = 64u * (unsigned)(t + 1);
            unsigned v;
            do {
                asm volatile("ld.acquire.gpu.global.u32 %0, [%1];"
                             : "=r"(v) : "l"(&g_cnt[l]) : "memory");
            } while (v < target);
        }
        __syncthreads();

        // stage h_t (swizzled dst: +1 float4 per 512-float4 slice)
        const float4* src = (const float4*)g_h[l][wb];
        float4* dst = (float4*)h_s;
#pragma unroll 4
        for (int i = tid; i < 4096; i += 256) {
            dst[i + (i >> 9)] = __ldcg(&src[i]);
        }
        __syncthreads();
    }

    size_t OUTH = (size_t)T_STEPS * BATCH * HID;
    out[OUTH + (size_t)l * BATCH * HID + b * 256 + hcol]                   = h_cur;
    out[OUTH + (size_t)NLAYER * BATCH * HID + (size_t)l * BATCH * HID
        + b * 256 + hcol]                                                   = c;
}

// ---------------- launch ----------------------------------------------------
extern "C" void kernel_launch(void* const* d_in, const int* in_sizes, int n_in,
                              void* d_out, int out_size) {
    const float* x    = (const float*)d_in[0];
    const float* h0   = (const float*)d_in[1];
    const float* c0   = (const float*)d_in[2];
    const float* W    = (const float*)d_in[3];
    const float* bias = (const float*)d_in[4];
    float* out = (float*)d_out;

    size_t dsmem = (size_t)(8 * HS_SLICE) * sizeof(float);   // 65,664 B
    cudaFuncSetAttribute(k_rec, cudaFuncAttributeMaxDynamicSharedMemorySize,
                         (int)dsmem);

    k_pre<<<NLAYER * (MROWS / 128) * (1024 / 128), 256>>>(x, W, bias);
    k_rec<<<NLAYER * 64, 256, dsmem>>>(h0, c0, W, out);
}